// round 1
// baseline (speedup 1.0000x reference)
#include <cuda_runtime.h>
#include <cuda_bf16.h>
#include <math.h>
#include <stdint.h>

// Problem constants
#define BB 64
#define HH 1024
#define EE 1024
#define SS 1024
#define VV 32000
#define KIH 2048   // E + H
#define G3H 3072   // 3*H

// ---------------- scratch (static device globals; no allocation) ----------------
__device__ float g_x0[BB * KIH];          // [b][k]  (emb | last_context)
__device__ float g_gia[G3H * BB];         // gi partial (k 0..1023)   [n][b]
__device__ float g_gib[G3H * BB];         // gi partial (k 1024..2047)[n][b]
__device__ float g_gh [G3H * BB];         // gh                        [n][b]
__device__ float g_z  [BB * KIH];         // [b][ h(1024) | ctx(1024) ]
__device__ float g_energy[BB * SS];       // raw attention energies [b][s]
__device__ float g_pm[BB * 8];            // per-chunk running max
__device__ float g_pl[BB * 8];            // per-chunk running sum
__device__ float g_pacc[BB * 8 * HH];     // per-chunk context accumulators
__device__ float g_logits[BB * VV];       // [b][v]

// ---------------- helpers ----------------
__device__ __forceinline__ void ffma2(unsigned long long& d,
                                      unsigned long long a,
                                      unsigned long long b) {
    asm("fma.rn.f32x2 %0, %1, %2, %0;" : "+l"(d) : "l"(a), "l"(b));
}

__device__ __forceinline__ float f2sum(unsigned long long u) {
    float lo, hi;
    asm("mov.b64 {%0, %1}, %2;" : "=f"(lo), "=f"(hi) : "l"(u));
    return lo + hi;
}

__device__ __forceinline__ float warpRedSum(float v) {
    #pragma unroll
    for (int o = 16; o; o >>= 1) v += __shfl_xor_sync(0xffffffffu, v, o);
    return v;
}
__device__ __forceinline__ float warpRedMax(float v) {
    #pragma unroll
    for (int o = 16; o; o >>= 1) v = fmaxf(v, __shfl_xor_sync(0xffffffffu, v, o));
    return v;
}

// block reduce for lsm kernel (up to 512 threads); returns result to all threads
__device__ __forceinline__ float blockRedMax(float v, float* sm) {
    v = warpRedMax(v);
    int w = threadIdx.x >> 5;
    __syncthreads();
    if ((threadIdx.x & 31) == 0) sm[w] = v;
    __syncthreads();
    float r = -INFINITY;
    int nw = blockDim.x >> 5;
    for (int i = 0; i < nw; ++i) r = fmaxf(r, sm[i]);
    return r;
}
__device__ __forceinline__ float blockRedSum(float v, float* sm) {
    v = warpRedSum(v);
    int w = threadIdx.x >> 5;
    __syncthreads();
    if ((threadIdx.x & 31) == 0) sm[w] = v;
    __syncthreads();
    float r = 0.f;
    int nw = blockDim.x >> 5;
    for (int i = 0; i < nw; ++i) r += sm[i];
    return r;
}

// ---------------- GEMM core: OUT[n][b] = sum_k W[n][k] * X[b][k] ----------------
// 64 n  x 64 b tile per block, 256 threads, 4b x 4n per thread, f32x2 FMAs.
// OUT_B_CONTIG: true  -> OUT addr = n*sn + b (sb==1), float4 store over b
//               false -> OUT addr = b*sb + n (sn==1), float4 store over n
template <bool OUT_B_CONTIG>
__device__ __forceinline__ void gemm_core(
    const float* __restrict__ W, int ldw,
    const float* __restrict__ X, int ldx,
    int K, float* __restrict__ OUT, int sn, int sb, int n0)
{
    const int tid = threadIdx.x;
    const int bq = tid & 15;        // 16 b-groups
    const int nq = tid >> 4;        // 16 n-groups
    const int b0  = bq * 4;
    const int n0t = n0 + nq * 4;

    unsigned long long acc[4][4];
    #pragma unroll
    for (int i = 0; i < 4; ++i)
        #pragma unroll
        for (int j = 0; j < 4; ++j) acc[i][j] = 0ull;

    const float* xrow0 = X + (long)(b0 + 0) * ldx;
    const float* xrow1 = X + (long)(b0 + 1) * ldx;
    const float* xrow2 = X + (long)(b0 + 2) * ldx;
    const float* xrow3 = X + (long)(b0 + 3) * ldx;
    const float* wrow0 = W + (long)(n0t + 0) * ldw;
    const float* wrow1 = W + (long)(n0t + 1) * ldw;
    const float* wrow2 = W + (long)(n0t + 2) * ldw;
    const float* wrow3 = W + (long)(n0t + 3) * ldw;

    #pragma unroll 2
    for (int k = 0; k < K; k += 4) {
        ulonglong2 xv[4], wv[4];
        xv[0] = *(const ulonglong2*)(xrow0 + k);
        xv[1] = *(const ulonglong2*)(xrow1 + k);
        xv[2] = *(const ulonglong2*)(xrow2 + k);
        xv[3] = *(const ulonglong2*)(xrow3 + k);
        wv[0] = *(const ulonglong2*)(wrow0 + k);
        wv[1] = *(const ulonglong2*)(wrow1 + k);
        wv[2] = *(const ulonglong2*)(wrow2 + k);
        wv[3] = *(const ulonglong2*)(wrow3 + k);
        #pragma unroll
        for (int i = 0; i < 4; ++i) {
            #pragma unroll
            for (int j = 0; j < 4; ++j) {
                ffma2(acc[i][j], xv[i].x, wv[j].x);
                ffma2(acc[i][j], xv[i].y, wv[j].y);
            }
        }
    }

    float res[4][4];
    #pragma unroll
    for (int i = 0; i < 4; ++i)
        #pragma unroll
        for (int j = 0; j < 4; ++j) res[i][j] = f2sum(acc[i][j]);

    if (OUT_B_CONTIG) {
        #pragma unroll
        for (int j = 0; j < 4; ++j) {
            float4 v = make_float4(res[0][j], res[1][j], res[2][j], res[3][j]);
            *(float4*)(OUT + (long)(n0t + j) * sn + b0) = v;
        }
    } else {
        #pragma unroll
        for (int i = 0; i < 4; ++i) {
            float4 v = make_float4(res[i][0], res[i][1], res[i][2], res[i][3]);
            *(float4*)(OUT + (long)(b0 + i) * sb + n0t) = v;
        }
    }
}

// ---------------- kernels ----------------

// x0 = [ emb_table[word[b]] | last_context[b] ]
__global__ void prep_kernel(const int* __restrict__ wi,
                            const float* __restrict__ lctx,
                            const float* __restrict__ emb)
{
    int t = blockIdx.x * blockDim.x + threadIdx.x;   // 131072 threads
    int b = t >> 11;
    int k = t & 2047;
    float v;
    if (k < 1024) v = emb[(long)wi[b] * EE + k];
    else          v = lctx[(long)b * HH + (k - 1024)];
    g_x0[t] = v;
}

// 144 tiles: [0,48) gi part0 (k<1024), [48,96) gi part1, [96,144) gh
__global__ void __launch_bounds__(256, 2) gates_kernel(
    const float* __restrict__ wih,
    const float* __restrict__ whh,
    const float* __restrict__ hprev)
{
    int t = blockIdx.x;
    if (t < 48) {
        gemm_core<true>(wih,        KIH, g_x0,        KIH, 1024, g_gia, BB, 1, t * 64);
    } else if (t < 96) {
        gemm_core<true>(wih + 1024, KIH, g_x0 + 1024, KIH, 1024, g_gib, BB, 1, (t - 48) * 64);
    } else {
        gemm_core<true>(whh,        HH,  hprev,       HH,  1024, g_gh,  BB, 1, (t - 96) * 64);
    }
}

// GRU gate nonlinearity -> h; h goes into g_z[:,0:1024] and the hidden output
__global__ void gru_kernel(const float* __restrict__ bih,
                           const float* __restrict__ bhh,
                           const float* __restrict__ hprev,
                           float* __restrict__ out_hidden)
{
    int t = blockIdx.x * blockDim.x + threadIdx.x;   // 65536
    int b = t & 63;
    int j = t >> 6;
    float gir = g_gia[(long)j * BB + b] + g_gib[(long)j * BB + b] + bih[j];
    float ghr = g_gh [(long)j * BB + b] + bhh[j];
    int jz = j + 1024;
    float giz = g_gia[(long)jz * BB + b] + g_gib[(long)jz * BB + b] + bih[jz];
    float ghz = g_gh [(long)jz * BB + b] + bhh[jz];
    int jn = j + 2048;
    float gin = g_gia[(long)jn * BB + b] + g_gib[(long)jn * BB + b] + bih[jn];
    float ghn = g_gh [(long)jn * BB + b] + bhh[jn];

    float r  = 1.f / (1.f + __expf(-(gir + ghr)));
    float zg = 1.f / (1.f + __expf(-(giz + ghz)));
    float ng = tanhf(gin + r * ghn);
    float hp = hprev[(long)b * HH + j];
    float h  = (1.f - zg) * ng + zg * hp;

    g_z[(long)b * KIH + j] = h;
    out_hidden[(long)b * HH + j] = h;
}

// flash-style attention over one S-chunk: energies + online softmax + partial context
__global__ void attn_kernel(const float* __restrict__ enc)
{
    int b = blockIdx.x >> 3;
    int c = blockIdx.x & 7;
    int tid = threadIdx.x;   // 256, each owns 4 h-elements

    float4 hv = *(const float4*)(g_z + (long)b * KIH + tid * 4);

    __shared__ float red[2][8];

    float m = -INFINITY, l = 0.f;
    float4 acc = make_float4(0.f, 0.f, 0.f, 0.f);
    int s0 = c * 128;

    const float4* ep = (const float4*)enc;
    // element index of enc[s][b][h4=tid]: ((s*64+b)*1024)/4 + tid
    float4 ev = ep[((long)(s0 * 64 + b)) * 256 + tid];

    for (int si = 0; si < 128; ++si) {
        int s = s0 + si;
        float4 evn = make_float4(0.f, 0.f, 0.f, 0.f);
        if (si < 127) evn = ep[((long)((s + 1) * 64 + b)) * 256 + tid];

        float p = ev.x * hv.x + ev.y * hv.y + ev.z * hv.z + ev.w * hv.w;
        p = warpRedSum(p);
        int par = si & 1;
        if ((tid & 31) == 0) red[par][tid >> 5] = p;
        __syncthreads();
        float e = red[par][0] + red[par][1] + red[par][2] + red[par][3]
                + red[par][4] + red[par][5] + red[par][6] + red[par][7];

        if (tid == 0) g_energy[(long)b * SS + s] = e;

        float mn = fmaxf(m, e);
        float sc = __expf(m - mn);     // 0 on first iter (m = -inf)
        float pe = __expf(e - mn);
        l = l * sc + pe;
        acc.x = acc.x * sc + pe * ev.x;
        acc.y = acc.y * sc + pe * ev.y;
        acc.z = acc.z * sc + pe * ev.z;
        acc.w = acc.w * sc + pe * ev.w;
        m = mn;
        ev = evn;
    }

    *(float4*)(g_pacc + ((long)(b * 8 + c)) * HH + tid * 4) = acc;
    if (tid == 0) { g_pm[b * 8 + c] = m; g_pl[b * 8 + c] = l; }
}

// merge the 8 chunks: context + normalized attention weights
__global__ void attn_combine(float* __restrict__ out_context,
                             float* __restrict__ out_attn)
{
    int b = blockIdx.x;
    int tid = threadIdx.x;   // 256

    float M = -INFINITY;
    #pragma unroll
    for (int c = 0; c < 8; ++c) M = fmaxf(M, g_pm[b * 8 + c]);
    float L = 0.f;
    float coef[8];
    #pragma unroll
    for (int c = 0; c < 8; ++c) {
        coef[c] = __expf(g_pm[b * 8 + c] - M);
        L += g_pl[b * 8 + c] * coef[c];
    }
    float invL = 1.f / L;

    float4 ctx = make_float4(0.f, 0.f, 0.f, 0.f);
    #pragma unroll
    for (int c = 0; c < 8; ++c) {
        float4 pa = *(const float4*)(g_pacc + ((long)(b * 8 + c)) * HH + tid * 4);
        ctx.x += coef[c] * pa.x;
        ctx.y += coef[c] * pa.y;
        ctx.z += coef[c] * pa.z;
        ctx.w += coef[c] * pa.w;
    }
    ctx.x *= invL; ctx.y *= invL; ctx.z *= invL; ctx.w *= invL;

    *(float4*)(g_z + (long)b * KIH + 1024 + tid * 4) = ctx;
    *(float4*)(out_context + (long)b * HH + tid * 4) = ctx;

    for (int s = tid; s < SS; s += 256) {
        float w = __expf(g_energy[(long)b * SS + s] - M) * invL;
        out_attn[(long)b * SS + s] = w;
    }
}

// logits[b][v] = z[b] . out_W[v]
__global__ void __launch_bounds__(256, 2) logits_kernel(const float* __restrict__ outW)
{
    gemm_core<false>(outW, KIH, g_z, KIH, KIH, g_logits, 1, VV, blockIdx.x * 64);
}

// per-b log_softmax over V (bias added here)
__global__ void lsm_kernel(const float* __restrict__ outb,
                           float* __restrict__ out)
{
    int b = blockIdx.x;
    int tid = threadIdx.x;   // 512
    __shared__ float sm[32];
    const float* row = g_logits + (long)b * VV;

    float m = -INFINITY;
    for (int v = tid; v < VV; v += 512) m = fmaxf(m, row[v] + outb[v]);
    m = blockRedMax(m, sm);

    float s = 0.f;
    for (int v = tid; v < VV; v += 512) s += __expf(row[v] + outb[v] - m);
    s = blockRedSum(s, sm);

    float lse = m + logf(s);
    for (int v = tid; v < VV; v += 512)
        out[(long)b * VV + v] = (row[v] + outb[v]) - lse;
}

// ---------------- launch ----------------
extern "C" void kernel_launch(void* const* d_in, const int* in_sizes, int n_in,
                              void* d_out, int out_size)
{
    const int*   wi   = (const int*)  d_in[0];   // word_input (1,B)
    const float* lctx = (const float*)d_in[1];   // last_context (B,H)
    const float* lhid = (const float*)d_in[2];   // last_hidden (1,B,H)
    const float* enc  = (const float*)d_in[3];   // encoder_outputs (S,B,H)
    const float* emb  = (const float*)d_in[4];   // emb_table (V,E)
    const float* wih  = (const float*)d_in[5];   // (3H, E+H)
    const float* whh  = (const float*)d_in[6];   // (3H, H)
    const float* bih  = (const float*)d_in[7];
    const float* bhh  = (const float*)d_in[8];
    const float* outW = (const float*)d_in[9];   // (V, 2H)
    const float* outb = (const float*)d_in[10];

    float* out        = (float*)d_out;
    float* out_output = out;                         // (B, V)
    float* out_ctx    = out + (long)BB * VV;         // (B, H)
    float* out_hid    = out_ctx + (long)BB * HH;     // (1, B, H)
    float* out_attn   = out_hid + (long)BB * HH;     // (B, 1, S)

    prep_kernel  <<<512, 256>>>(wi, lctx, emb);
    gates_kernel <<<144, 256>>>(wih, whh, lhid);
    gru_kernel   <<<256, 256>>>(bih, bhh, lhid, out_hid);
    attn_kernel  <<<512, 256>>>(enc);
    attn_combine <<<64, 256>>>(out_ctx, out_attn);
    logits_kernel<<<500, 256>>>(outW);
    lsm_kernel   <<<64, 512>>>(outb, out_output);
}

// round 4
// speedup vs baseline: 5.1757x; 5.1757x over previous
#include <cuda_runtime.h>
#include <cuda_bf16.h>
#include <math.h>
#include <stdint.h>

// Problem constants
#define BB 64
#define HH 1024
#define SS_ 1024
#define VV 32000
#define KIH 2048   // E + H
#define G3H 3072   // 3*H

// ---------------- scratch (static device globals) ----------------
__device__ __nv_bfloat16 g_x0hi[BB * KIH];
__device__ __nv_bfloat16 g_x0lo[BB * KIH];
__device__ __nv_bfloat16 g_hhi [BB * HH];
__device__ __nv_bfloat16 g_hlo [BB * HH];
__device__ __nv_bfloat16 g_zhi [BB * KIH];   // [b][ h | ctx ]
__device__ __nv_bfloat16 g_zlo [BB * KIH];
__device__ float g_gi[BB * G3H];             // [b][n]
__device__ float g_gh[BB * G3H];             // [b][n]
__device__ float g_z [BB * KIH];             // fp32 h (attn uses [0,1024))
__device__ float g_energy[BB * SS_];
__device__ float g_pm[BB * 8];
__device__ float g_pl[BB * 8];
__device__ float g_pacc[BB * 8 * HH];
__device__ float g_logits[BB * VV];

// ---------------- helpers ----------------
__device__ __forceinline__ uint32_t smem_u32(const void* p) {
    uint32_t a;
    asm("{ .reg .u64 t; cvta.to.shared.u64 t, %1; cvt.u32.u64 %0, t; }" : "=r"(a) : "l"(p));
    return a;
}
__device__ __forceinline__ void ldm_x4(uint32_t& r0, uint32_t& r1, uint32_t& r2, uint32_t& r3,
                                       uint32_t addr) {
    asm volatile("ldmatrix.sync.aligned.m8n8.x4.shared.b16 {%0,%1,%2,%3}, [%4];"
        : "=r"(r0), "=r"(r1), "=r"(r2), "=r"(r3) : "r"(addr));
}
__device__ __forceinline__ void mma_bf16(float* c, const uint32_t* a, const uint32_t* b) {
    asm volatile("mma.sync.aligned.m16n8k16.row.col.f32.bf16.bf16.f32 "
        "{%0,%1,%2,%3}, {%4,%5,%6,%7}, {%8,%9}, {%0,%1,%2,%3};"
        : "+f"(c[0]), "+f"(c[1]), "+f"(c[2]), "+f"(c[3])
        : "r"(a[0]), "r"(a[1]), "r"(a[2]), "r"(a[3]), "r"(b[0]), "r"(b[1]));
}

__device__ __forceinline__ float warpRedSum(float v) {
    #pragma unroll
    for (int o = 16; o; o >>= 1) v += __shfl_xor_sync(0xffffffffu, v, o);
    return v;
}
__device__ __forceinline__ float warpRedMax(float v) {
    #pragma unroll
    for (int o = 16; o; o >>= 1) v = fmaxf(v, __shfl_xor_sync(0xffffffffu, v, o));
    return v;
}

// smem geometry for the MMA GEMM
#define PITCH  72                      // bf16 elements per smem row (144 B, conflict-free)
#define ABYTES (128 * PITCH * 2)       // 18432: 64 hi rows + 64 lo rows
#define WOFF   ABYTES
#define BUFSZ  (2 * ABYTES)            // 36864 per buffer (A + W)
#define SMEM_GEMM (2 * BUFSZ)          // 73728 double-buffered

// ============ mma.sync split-bf16 GEMM ============
// OUT[b][n0+n] = sum_k A[b][k] * W[n0+n][k],  A = Ahi + Alo (bf16 split), W fp32.
// D = Ahi*Whi + Ahi*Wlo + Alo*Whi  (lo*lo dropped).  ldw == K (row-major, dense).
__device__ __forceinline__ void mma_gemm(
    const float* __restrict__ W, int K,
    const __nv_bfloat16* __restrict__ Ahi, const __nv_bfloat16* __restrict__ Alo,
    float* __restrict__ OUT, int ldout, int n0)
{
    extern __shared__ char smem[];
    const uint32_t sbase = smem_u32(smem);
    const int tid = threadIdx.x;
    const int w = tid >> 5, l = tid & 31;
    const int wm = w >> 2;          // 0/1 : rows wm*32..+31
    const int wn = w & 3;           // 0..3: cols wn*16..+15
    const int nch = K >> 6;

    // A staging: thread -> row (0..127: 64 hi + 64 lo), 32 elements (half of k-chunk)
    const int ar   = tid >> 1;
    const int aseg = (tid & 1) * 32;
    const __nv_bfloat16* asrc =
        (ar < 64 ? Ahi + (long)ar * K : Alo + (long)(ar - 64) * K) + aseg;
    const int adst = (ar * PITCH + aseg) * 2;

    // W staging: thread -> n-row (0..63), 16 k-floats
    const int wr   = tid >> 2;
    const int wseg = (tid & 3) * 16;
    const float* wsrc = W + (long)(n0 + wr) * K + wseg;
    const int wdst_hi = (wr * PITCH + wseg) * 2;
    const int wdst_lo = ((wr + 64) * PITCH + wseg) * 2;

    float acc[2][2][4];
    #pragma unroll
    for (int i = 0; i < 2; ++i)
        #pragma unroll
        for (int j = 0; j < 2; ++j)
            #pragma unroll
            for (int q = 0; q < 4; ++q) acc[i][j][q] = 0.f;

    uint4  stA[4];
    float4 stW[4];

    // prologue: load chunk 0
    #pragma unroll
    for (int i = 0; i < 4; ++i) stA[i] = *(const uint4*)(asrc + i * 8);
    #pragma unroll
    for (int i = 0; i < 4; ++i) stW[i] = *(const float4*)(wsrc + i * 4);
    {
        char* bufA = smem;
        char* bufW = smem + WOFF;
        #pragma unroll
        for (int i = 0; i < 4; ++i) *(uint4*)(bufA + adst + i * 16) = stA[i];
        #pragma unroll
        for (int i = 0; i < 4; ++i) {
            float4 x = stW[i];
            __nv_bfloat162 h0 = __floats2bfloat162_rn(x.x, x.y);
            __nv_bfloat162 h1 = __floats2bfloat162_rn(x.z, x.w);
            __nv_bfloat162 l0 = __floats2bfloat162_rn(x.x - __bfloat162float(h0.x),
                                                      x.y - __bfloat162float(h0.y));
            __nv_bfloat162 l1 = __floats2bfloat162_rn(x.z - __bfloat162float(h1.x),
                                                      x.w - __bfloat162float(h1.y));
            uint2 hp, lp;
            hp.x = *(uint32_t*)&h0; hp.y = *(uint32_t*)&h1;
            lp.x = *(uint32_t*)&l0; lp.y = *(uint32_t*)&l1;
            *(uint2*)(bufW + wdst_hi + i * 8) = hp;
            *(uint2*)(bufW + wdst_lo + i * 8) = lp;
        }
    }
    __syncthreads();

    for (int c = 0; c < nch; ++c) {
        const int cur = c & 1;
        if (c + 1 < nch) {
            const __nv_bfloat16* as = asrc + (c + 1) * 64;
            #pragma unroll
            for (int i = 0; i < 4; ++i) stA[i] = *(const uint4*)(as + i * 8);
            const float* ws = wsrc + (c + 1) * 64;
            #pragma unroll
            for (int i = 0; i < 4; ++i) stW[i] = *(const float4*)(ws + i * 4);
        }
        const uint32_t sA = sbase + cur * BUFSZ;
        const uint32_t sW = sA + WOFF;

        #pragma unroll
        for (int ks = 0; ks < 4; ++ks) {
            const int k = ks * 16;
            uint32_t ah[2][4], al[2][4], bh[4], bl[4];
            const int rowa = l & 15;
            const int cola = k + (l >> 4) * 8;
            #pragma unroll
            for (int mt = 0; mt < 2; ++mt) {
                const int rhi = wm * 32 + mt * 16 + rowa;
                ldm_x4(ah[mt][0], ah[mt][1], ah[mt][2], ah[mt][3],
                       sA + (rhi * PITCH + cola) * 2);
                ldm_x4(al[mt][0], al[mt][1], al[mt][2], al[mt][3],
                       sA + ((rhi + 64) * PITCH + cola) * 2);
            }
            const int rowb = wn * 16 + ((l >> 4) << 3) + (l & 7);
            const int colb = k + ((l >> 3) & 1) * 8;
            ldm_x4(bh[0], bh[1], bh[2], bh[3], sW + (rowb * PITCH + colb) * 2);
            ldm_x4(bl[0], bl[1], bl[2], bl[3], sW + ((rowb + 64) * PITCH + colb) * 2);

            #pragma unroll
            for (int mt = 0; mt < 2; ++mt)
                #pragma unroll
                for (int nt = 0; nt < 2; ++nt) {
                    mma_bf16(acc[mt][nt], ah[mt], &bh[nt * 2]);
                    mma_bf16(acc[mt][nt], ah[mt], &bl[nt * 2]);
                    mma_bf16(acc[mt][nt], al[mt], &bh[nt * 2]);
                }
        }

        if (c + 1 < nch) {
            char* bufA = smem + (cur ^ 1) * BUFSZ;
            char* bufW = bufA + WOFF;
            #pragma unroll
            for (int i = 0; i < 4; ++i) *(uint4*)(bufA + adst + i * 16) = stA[i];
            #pragma unroll
            for (int i = 0; i < 4; ++i) {
                float4 x = stW[i];
                __nv_bfloat162 h0 = __floats2bfloat162_rn(x.x, x.y);
                __nv_bfloat162 h1 = __floats2bfloat162_rn(x.z, x.w);
                __nv_bfloat162 l0 = __floats2bfloat162_rn(x.x - __bfloat162float(h0.x),
                                                          x.y - __bfloat162float(h0.y));
                __nv_bfloat162 l1 = __floats2bfloat162_rn(x.z - __bfloat162float(h1.x),
                                                          x.w - __bfloat162float(h1.y));
                uint2 hp, lp;
                hp.x = *(uint32_t*)&h0; hp.y = *(uint32_t*)&h1;
                lp.x = *(uint32_t*)&l0; lp.y = *(uint32_t*)&l1;
                *(uint2*)(bufW + wdst_hi + i * 8) = hp;
                *(uint2*)(bufW + wdst_lo + i * 8) = lp;
            }
        }
        __syncthreads();
    }

    // epilogue: direct register -> global (fragment layout m16n8)
    #pragma unroll
    for (int mt = 0; mt < 2; ++mt) {
        #pragma unroll
        for (int nt = 0; nt < 2; ++nt) {
            const int row = wm * 32 + mt * 16 + (l >> 2);
            const int col = n0 + wn * 16 + nt * 8 + (l & 3) * 2;
            float2 v0 = make_float2(acc[mt][nt][0], acc[mt][nt][1]);
            float2 v1 = make_float2(acc[mt][nt][2], acc[mt][nt][3]);
            *(float2*)(OUT + (long)row * ldout + col)       = v0;
            *(float2*)(OUT + (long)(row + 8) * ldout + col) = v1;
        }
    }
}

// ---------------- kernels ----------------

// split x0 = [emb|lctx] and hprev into bf16 hi/lo
__global__ void prep_kernel(const int* __restrict__ wi,
                            const float* __restrict__ lctx,
                            const float* __restrict__ emb,
                            const float* __restrict__ lhid)
{
    int t = blockIdx.x * blockDim.x + threadIdx.x;   // 196608
    if (t < BB * KIH) {
        int b = t >> 11, k = t & 2047;
        float x = (k < 1024) ? emb[(long)wi[b] * 1024 + k] : lctx[(long)b * HH + (k - 1024)];
        __nv_bfloat16 h = __float2bfloat16(x);
        g_x0hi[t] = h;
        g_x0lo[t] = __float2bfloat16(x - __bfloat162float(h));
    } else {
        int t2 = t - BB * KIH;
        float x = lhid[t2];
        __nv_bfloat16 h = __float2bfloat16(x);
        g_hhi[t2] = h;
        g_hlo[t2] = __float2bfloat16(x - __bfloat162float(h));
    }
}

__global__ void __launch_bounds__(256, 2) gates_mma_kernel(
    const float* __restrict__ wih, const float* __restrict__ whh)
{
    if (blockIdx.x < 48)
        mma_gemm(wih, KIH, g_x0hi, g_x0lo, g_gi, G3H, blockIdx.x * 64);
    else
        mma_gemm(whh, HH, g_hhi, g_hlo, g_gh, G3H, (blockIdx.x - 48) * 64);
}

__global__ void __launch_bounds__(256, 2) logits_mma_kernel(const float* __restrict__ outW)
{
    mma_gemm(outW, KIH, g_zhi, g_zlo, g_logits, VV, blockIdx.x * 64);
}

// GRU gate nonlinearity -> h (fp32 + bf16 hi/lo); coalesced indexing
__global__ void gru_kernel(const float* __restrict__ bih,
                           const float* __restrict__ bhh,
                           const float* __restrict__ hprev,
                           float* __restrict__ out_hidden)
{
    int t = blockIdx.x * blockDim.x + threadIdx.x;   // 65536
    int b = t >> 10;
    int j = t & 1023;
    const float* gi = g_gi + (long)b * G3H;
    const float* gh = g_gh + (long)b * G3H;
    float r  = 1.f / (1.f + __expf(-((gi[j]        + bih[j])        + (gh[j]        + bhh[j]))));
    float zg = 1.f / (1.f + __expf(-((gi[j + 1024] + bih[j + 1024]) + (gh[j + 1024] + bhh[j + 1024]))));
    float ng = tanhf((gi[j + 2048] + bih[j + 2048]) + r * (gh[j + 2048] + bhh[j + 2048]));
    float hp = hprev[(long)b * HH + j];
    float h  = (1.f - zg) * ng + zg * hp;

    g_z[(long)b * KIH + j] = h;
    out_hidden[(long)b * HH + j] = h;
    __nv_bfloat16 hh = __float2bfloat16(h);
    g_zhi[(long)b * KIH + j] = hh;
    g_zlo[(long)b * KIH + j] = __float2bfloat16(h - __bfloat162float(hh));
}

// flash attention, batch-8 s per iteration
__global__ void attn_kernel(const float* __restrict__ enc)
{
    const int b = blockIdx.x >> 3;
    const int c = blockIdx.x & 7;
    const int tid = threadIdx.x;
    const int wd = tid >> 5, ln = tid & 31;

    float4 hv = *(const float4*)(g_z + (long)b * KIH + tid * 4);

    __shared__ float part[8][8];
    __shared__ float evals[8];

    float m = -INFINITY, l = 0.f;
    float4 acc = make_float4(0.f, 0.f, 0.f, 0.f);

    for (int it = 0; it < 16; ++it) {
        const int s0 = c * 128 + it * 8;
        float4 ev[8];
        #pragma unroll
        for (int i = 0; i < 8; ++i)
            ev[i] = *(const float4*)(enc + ((long)(s0 + i) * 64 + b) * 1024 + tid * 4);
        #pragma unroll
        for (int i = 0; i < 8; ++i) {
            float p = ev[i].x * hv.x + ev[i].y * hv.y + ev[i].z * hv.z + ev[i].w * hv.w;
            p = warpRedSum(p);
            if (ln == 0) part[i][wd] = p;
        }
        __syncthreads();
        if (tid < 8) {
            float e = part[tid][0] + part[tid][1] + part[tid][2] + part[tid][3]
                    + part[tid][4] + part[tid][5] + part[tid][6] + part[tid][7];
            evals[tid] = e;
            g_energy[(long)b * SS_ + s0 + tid] = e;
        }
        __syncthreads();
        #pragma unroll
        for (int i = 0; i < 8; ++i) {
            float e = evals[i];
            float mn = fmaxf(m, e);
            float sc = __expf(m - mn);
            float pe = __expf(e - mn);
            l = l * sc + pe;
            acc.x = acc.x * sc + pe * ev[i].x;
            acc.y = acc.y * sc + pe * ev[i].y;
            acc.z = acc.z * sc + pe * ev[i].z;
            acc.w = acc.w * sc + pe * ev[i].w;
            m = mn;
        }
    }

    *(float4*)(g_pacc + ((long)(b * 8 + c)) * HH + tid * 4) = acc;
    if (tid == 0) { g_pm[b * 8 + c] = m; g_pl[b * 8 + c] = l; }
}

// merge 8 chunks -> context (fp32 out + bf16 hi/lo into z), attn weights
__global__ void attn_combine(float* __restrict__ out_context,
                             float* __restrict__ out_attn)
{
    int b = blockIdx.x;
    int tid = threadIdx.x;   // 256

    float M = -INFINITY;
    #pragma unroll
    for (int c = 0; c < 8; ++c) M = fmaxf(M, g_pm[b * 8 + c]);
    float L = 0.f;
    float coef[8];
    #pragma unroll
    for (int c = 0; c < 8; ++c) {
        coef[c] = __expf(g_pm[b * 8 + c] - M);
        L += g_pl[b * 8 + c] * coef[c];
    }
    float invL = 1.f / L;

    float4 ctx = make_float4(0.f, 0.f, 0.f, 0.f);
    #pragma unroll
    for (int c = 0; c < 8; ++c) {
        float4 pa = *(const float4*)(g_pacc + ((long)(b * 8 + c)) * HH + tid * 4);
        ctx.x += coef[c] * pa.x;
        ctx.y += coef[c] * pa.y;
        ctx.z += coef[c] * pa.z;
        ctx.w += coef[c] * pa.w;
    }
    ctx.x *= invL; ctx.y *= invL; ctx.z *= invL; ctx.w *= invL;

    *(float4*)(out_context + (long)b * HH + tid * 4) = ctx;
    float cv[4] = {ctx.x, ctx.y, ctx.z, ctx.w};
    #pragma unroll
    for (int q = 0; q < 4; ++q) {
        __nv_bfloat16 h = __float2bfloat16(cv[q]);
        long idx = (long)b * KIH + 1024 + tid * 4 + q;
        g_zhi[idx] = h;
        g_zlo[idx] = __float2bfloat16(cv[q] - __bfloat162float(h));
    }

    for (int s = tid; s < SS_; s += 256) {
        float w = __expf(g_energy[(long)b * SS_ + s] - M) * invL;
        out_attn[(long)b * SS_ + s] = w;
    }
}

// per-b log_softmax over V (bias added here)
__global__ void lsm_kernel(const float* __restrict__ outb,
                           float* __restrict__ out)
{
    int b = blockIdx.x;
    int tid = threadIdx.x;   // 512
    __shared__ float sm[32];
    const float* row = g_logits + (long)b * VV;

    float m = -INFINITY;
    for (int v = tid; v < VV; v += 512) m = fmaxf(m, row[v] + outb[v]);
    m = warpRedMax(m);
    if ((tid & 31) == 0) sm[tid >> 5] = m;
    __syncthreads();
    float M = -INFINITY;
    for (int i = 0; i < 16; ++i) M = fmaxf(M, sm[i]);

    float s = 0.f;
    for (int v = tid; v < VV; v += 512) s += __expf(row[v] + outb[v] - M);
    s = warpRedSum(s);
    __syncthreads();
    if ((tid & 31) == 0) sm[tid >> 5] = s;
    __syncthreads();
    float S = 0.f;
    for (int i = 0; i < 16; ++i) S += sm[i];

    float lse = M + logf(S);
    for (int v = tid; v < VV; v += 512)
        out[(long)b * VV + v] = (row[v] + outb[v]) - lse;
}

// ---------------- launch ----------------
extern "C" void kernel_launch(void* const* d_in, const int* in_sizes, int n_in,
                              void* d_out, int out_size)
{
    const int*   wi   = (const int*)  d_in[0];
    const float* lctx = (const float*)d_in[1];
    const float* lhid = (const float*)d_in[2];
    const float* enc  = (const float*)d_in[3];
    const float* emb  = (const float*)d_in[4];
    const float* wih  = (const float*)d_in[5];
    const float* whh  = (const float*)d_in[6];
    const float* bih  = (const float*)d_in[7];
    const float* bhh  = (const float*)d_in[8];
    const float* outW = (const float*)d_in[9];
    const float* outb = (const float*)d_in[10];

    float* out        = (float*)d_out;
    float* out_output = out;                         // (B, V)
    float* out_ctx    = out + (long)BB * VV;         // (B, H)
    float* out_hid    = out_ctx + (long)BB * HH;     // (1, B, H)
    float* out_attn   = out_hid + (long)BB * HH;     // (B, 1, S)

    cudaFuncSetAttribute(gates_mma_kernel,  cudaFuncAttributeMaxDynamicSharedMemorySize, SMEM_GEMM);
    cudaFuncSetAttribute(logits_mma_kernel, cudaFuncAttributeMaxDynamicSharedMemorySize, SMEM_GEMM);

    prep_kernel      <<<768, 256>>>(wi, lctx, emb, lhid);
    gates_mma_kernel <<<96, 256, SMEM_GEMM>>>(wih, whh);
    gru_kernel       <<<256, 256>>>(bih, bhh, lhid, out_hid);
    attn_kernel      <<<512, 256>>>(enc);
    attn_combine     <<<64, 256>>>(out_ctx, out_attn);
    logits_mma_kernel<<<500, 256, SMEM_GEMM>>>(outW);
    lsm_kernel       <<<64, 512>>>(outb, out_output);
}

// round 5
// speedup vs baseline: 5.6157x; 1.0850x over previous
#include <cuda_runtime.h>
#include <cuda_bf16.h>
#include <math.h>
#include <stdint.h>

// Problem constants
#define BB 64
#define HH 1024
#define SS_ 1024
#define VV 32000
#define KIH 2048   // E + H
#define G3H 3072   // 3*H
#define NTILES 500 // logits tiles of 64 cols

// ---------------- scratch (static device globals) ----------------
__device__ __nv_bfloat16 g_x0hi[BB * KIH];
__device__ __nv_bfloat16 g_x0lo[BB * KIH];
__device__ __nv_bfloat16 g_hhi [BB * HH];
__device__ __nv_bfloat16 g_hlo [BB * HH];
__device__ __nv_bfloat16 g_zhi [BB * KIH];   // [b][ h | ctx ]
__device__ __nv_bfloat16 g_zlo [BB * KIH];
__device__ float g_gi[BB * G3H];             // [b][n]
__device__ float g_gh[BB * G3H];             // [b][n]
__device__ float g_z [BB * KIH];             // fp32 h (attn uses [0,1024))
__device__ float g_energy[BB * SS_];
__device__ float g_pm[BB * 8];
__device__ float g_pl[BB * 8];
__device__ float g_pacc[BB * 8 * HH];
__device__ float g_logits[BB * VV];          // biased logits
__device__ float g_tm[NTILES * BB];          // per-tile row max
__device__ float g_tl[NTILES * BB];          // per-tile row sumexp
__device__ float g_lse[BB];

// ---------------- helpers ----------------
__device__ __forceinline__ uint32_t smem_u32(const void* p) {
    uint32_t a;
    asm("{ .reg .u64 t; cvta.to.shared.u64 t, %1; cvt.u32.u64 %0, t; }" : "=r"(a) : "l"(p));
    return a;
}
__device__ __forceinline__ void ldm_x4(uint32_t& r0, uint32_t& r1, uint32_t& r2, uint32_t& r3,
                                       uint32_t addr) {
    asm volatile("ldmatrix.sync.aligned.m8n8.x4.shared.b16 {%0,%1,%2,%3}, [%4];"
        : "=r"(r0), "=r"(r1), "=r"(r2), "=r"(r3) : "r"(addr));
}
__device__ __forceinline__ void mma_bf16(float* c, const uint32_t* a, const uint32_t* b) {
    asm volatile("mma.sync.aligned.m16n8k16.row.col.f32.bf16.bf16.f32 "
        "{%0,%1,%2,%3}, {%4,%5,%6,%7}, {%8,%9}, {%0,%1,%2,%3};"
        : "+f"(c[0]), "+f"(c[1]), "+f"(c[2]), "+f"(c[3])
        : "r"(a[0]), "r"(a[1]), "r"(a[2]), "r"(a[3]), "r"(b[0]), "r"(b[1]));
}

__device__ __forceinline__ float warpRedSum(float v) {
    #pragma unroll
    for (int o = 16; o; o >>= 1) v += __shfl_xor_sync(0xffffffffu, v, o);
    return v;
}
__device__ __forceinline__ float warpRedMax(float v) {
    #pragma unroll
    for (int o = 16; o; o >>= 1) v = fmaxf(v, __shfl_xor_sync(0xffffffffu, v, o));
    return v;
}

// smem geometry for the MMA GEMM
#define PITCH  72                      // bf16 elements per smem row (144 B)
#define ABYTES (128 * PITCH * 2)       // 18432: 64 hi rows + 64 lo rows
#define WOFF   ABYTES
#define BUFSZ  (2 * ABYTES)            // 36864 per buffer (A + W)
#define SMEM_GEMM (2 * BUFSZ)          // 73728 double-buffered

// ============ mma.sync split-bf16 GEMM ============
// OUT[b][n0+n] = sum_k A[b][k] * W[n0+n][k],  A = Ahi + Alo (bf16 split), W fp32.
// D = Ahi*Whi + Ahi*Wlo + Alo*Whi  (lo*lo dropped).
// STATS: add bias, store biased, and emit per-tile row max / sumexp to g_tm/g_tl.
template <bool STATS>
__device__ __forceinline__ void mma_gemm(
    const float* __restrict__ W, int K,
    const __nv_bfloat16* __restrict__ Ahi, const __nv_bfloat16* __restrict__ Alo,
    float* __restrict__ OUT, int ldout, int n0,
    const float* __restrict__ bias, int tile)
{
    extern __shared__ char smem[];
    const uint32_t sbase = smem_u32(smem);
    const int tid = threadIdx.x;
    const int w = tid >> 5, l = tid & 31;
    const int wm = w >> 2;          // 0/1 : rows wm*32..+31
    const int wn = w & 3;           // 0..3: cols wn*16..+15
    const int nch = K >> 6;

    // A staging: thread -> row (0..127: 64 hi + 64 lo), 32 elements
    const int ar   = tid >> 1;
    const int aseg = (tid & 1) * 32;
    const __nv_bfloat16* asrc =
        (ar < 64 ? Ahi + (long)ar * K : Alo + (long)(ar - 64) * K) + aseg;
    const int adst = (ar * PITCH + aseg) * 2;

    // W staging: thread -> n-row (0..63), 16 k-floats
    const int wr   = tid >> 2;
    const int wseg = (tid & 3) * 16;
    const float* wsrc = W + (long)(n0 + wr) * K + wseg;
    const int wdst_hi = (wr * PITCH + wseg) * 2;
    const int wdst_lo = ((wr + 64) * PITCH + wseg) * 2;

    float acc[2][2][4];
    #pragma unroll
    for (int i = 0; i < 2; ++i)
        #pragma unroll
        for (int j = 0; j < 2; ++j)
            #pragma unroll
            for (int q = 0; q < 4; ++q) acc[i][j][q] = 0.f;

    uint4  stA[4];
    float4 stW[4];

    // prologue: load chunk 0
    #pragma unroll
    for (int i = 0; i < 4; ++i) stA[i] = *(const uint4*)(asrc + i * 8);
    #pragma unroll
    for (int i = 0; i < 4; ++i) stW[i] = *(const float4*)(wsrc + i * 4);
    {
        char* bufA = smem;
        char* bufW = smem + WOFF;
        #pragma unroll
        for (int i = 0; i < 4; ++i) *(uint4*)(bufA + adst + i * 16) = stA[i];
        #pragma unroll
        for (int i = 0; i < 4; ++i) {
            float4 x = stW[i];
            __nv_bfloat162 h0 = __floats2bfloat162_rn(x.x, x.y);
            __nv_bfloat162 h1 = __floats2bfloat162_rn(x.z, x.w);
            __nv_bfloat162 l0 = __floats2bfloat162_rn(x.x - __bfloat162float(h0.x),
                                                      x.y - __bfloat162float(h0.y));
            __nv_bfloat162 l1 = __floats2bfloat162_rn(x.z - __bfloat162float(h1.x),
                                                      x.w - __bfloat162float(h1.y));
            uint2 hp, lp;
            hp.x = *(uint32_t*)&h0; hp.y = *(uint32_t*)&h1;
            lp.x = *(uint32_t*)&l0; lp.y = *(uint32_t*)&l1;
            *(uint2*)(bufW + wdst_hi + i * 8) = hp;
            *(uint2*)(bufW + wdst_lo + i * 8) = lp;
        }
    }
    __syncthreads();

    for (int c = 0; c < nch; ++c) {
        const int cur = c & 1;
        if (c + 1 < nch) {
            const __nv_bfloat16* as = asrc + (c + 1) * 64;
            #pragma unroll
            for (int i = 0; i < 4; ++i) stA[i] = *(const uint4*)(as + i * 8);
            const float* ws = wsrc + (c + 1) * 64;
            #pragma unroll
            for (int i = 0; i < 4; ++i) stW[i] = *(const float4*)(ws + i * 4);
        }
        const uint32_t sA = sbase + cur * BUFSZ;
        const uint32_t sW = sA + WOFF;

        #pragma unroll
        for (int ks = 0; ks < 4; ++ks) {
            const int k = ks * 16;
            uint32_t ah[2][4], al[2][4], bh[4], bl[4];
            const int rowa = l & 15;
            const int cola = k + (l >> 4) * 8;
            #pragma unroll
            for (int mt = 0; mt < 2; ++mt) {
                const int rhi = wm * 32 + mt * 16 + rowa;
                ldm_x4(ah[mt][0], ah[mt][1], ah[mt][2], ah[mt][3],
                       sA + (rhi * PITCH + cola) * 2);
                ldm_x4(al[mt][0], al[mt][1], al[mt][2], al[mt][3],
                       sA + ((rhi + 64) * PITCH + cola) * 2);
            }
            const int rowb = wn * 16 + ((l >> 4) << 3) + (l & 7);
            const int colb = k + ((l >> 3) & 1) * 8;
            ldm_x4(bh[0], bh[1], bh[2], bh[3], sW + (rowb * PITCH + colb) * 2);
            ldm_x4(bl[0], bl[1], bl[2], bl[3], sW + ((rowb + 64) * PITCH + colb) * 2);

            #pragma unroll
            for (int mt = 0; mt < 2; ++mt)
                #pragma unroll
                for (int nt = 0; nt < 2; ++nt) {
                    mma_bf16(acc[mt][nt], ah[mt], &bh[nt * 2]);
                    mma_bf16(acc[mt][nt], ah[mt], &bl[nt * 2]);
                    mma_bf16(acc[mt][nt], al[mt], &bh[nt * 2]);
                }
        }

        if (c + 1 < nch) {
            char* bufA = smem + (cur ^ 1) * BUFSZ;
            char* bufW = bufA + WOFF;
            #pragma unroll
            for (int i = 0; i < 4; ++i) *(uint4*)(bufA + adst + i * 16) = stA[i];
            #pragma unroll
            for (int i = 0; i < 4; ++i) {
                float4 x = stW[i];
                __nv_bfloat162 h0 = __floats2bfloat162_rn(x.x, x.y);
                __nv_bfloat162 h1 = __floats2bfloat162_rn(x.z, x.w);
                __nv_bfloat162 l0 = __floats2bfloat162_rn(x.x - __bfloat162float(h0.x),
                                                          x.y - __bfloat162float(h0.y));
                __nv_bfloat162 l1 = __floats2bfloat162_rn(x.z - __bfloat162float(h1.x),
                                                          x.w - __bfloat162float(h1.y));
                uint2 hp, lp;
                hp.x = *(uint32_t*)&h0; hp.y = *(uint32_t*)&h1;
                lp.x = *(uint32_t*)&l0; lp.y = *(uint32_t*)&l1;
                *(uint2*)(bufW + wdst_hi + i * 8) = hp;
                *(uint2*)(bufW + wdst_lo + i * 8) = lp;
            }
        }
        __syncthreads();
    }

    // optional bias add
    if (STATS) {
        #pragma unroll
        for (int nt = 0; nt < 2; ++nt) {
            const int col = n0 + wn * 16 + nt * 8 + (l & 3) * 2;
            float2 bb = *(const float2*)(bias + col);
            #pragma unroll
            for (int mt = 0; mt < 2; ++mt) {
                acc[mt][nt][0] += bb.x; acc[mt][nt][1] += bb.y;
                acc[mt][nt][2] += bb.x; acc[mt][nt][3] += bb.y;
            }
        }
    }

    // store (fragment layout m16n8)
    #pragma unroll
    for (int mt = 0; mt < 2; ++mt) {
        #pragma unroll
        for (int nt = 0; nt < 2; ++nt) {
            const int row = wm * 32 + mt * 16 + (l >> 2);
            const int col = n0 + wn * 16 + nt * 8 + (l & 3) * 2;
            float2 v0 = make_float2(acc[mt][nt][0], acc[mt][nt][1]);
            float2 v1 = make_float2(acc[mt][nt][2], acc[mt][nt][3]);
            *(float2*)(OUT + (long)row * ldout + col)       = v0;
            *(float2*)(OUT + (long)(row + 8) * ldout + col) = v1;
        }
    }

    if (STATS) {
        // per-row (b) max + sumexp over this tile's 64 cols
        float* sm_em = (float*)smem;         // [4][64]
        float* sm_el = sm_em + 256;          // [4][64]
        float rmax[4], rsum[4];
        // r = mt*2 + half; vals: acc[mt][0][half*2+j], acc[mt][1][half*2+j]
        #pragma unroll
        for (int r = 0; r < 4; ++r) {
            const int mt = r >> 1, hf = r & 1;
            float v = fmaxf(fmaxf(acc[mt][0][hf * 2], acc[mt][0][hf * 2 + 1]),
                            fmaxf(acc[mt][1][hf * 2], acc[mt][1][hf * 2 + 1]));
            v = fmaxf(v, __shfl_xor_sync(0xffffffffu, v, 1));
            v = fmaxf(v, __shfl_xor_sync(0xffffffffu, v, 2));
            rmax[r] = v;
        }
        if ((l & 3) == 0) {
            #pragma unroll
            for (int r = 0; r < 4; ++r) {
                const int mt = r >> 1, hf = r & 1;
                const int row = wm * 32 + mt * 16 + hf * 8 + (l >> 2);
                sm_em[wn * 64 + row] = rmax[r];
            }
        }
        __syncthreads();
        #pragma unroll
        for (int r = 0; r < 4; ++r) {
            const int mt = r >> 1, hf = r & 1;
            const int row = wm * 32 + mt * 16 + hf * 8 + (l >> 2);
            float gm = fmaxf(fmaxf(sm_em[row], sm_em[64 + row]),
                             fmaxf(sm_em[128 + row], sm_em[192 + row]));
            rmax[r] = gm;
            float s = __expf(acc[mt][0][hf * 2]     - gm) + __expf(acc[mt][0][hf * 2 + 1] - gm)
                    + __expf(acc[mt][1][hf * 2]     - gm) + __expf(acc[mt][1][hf * 2 + 1] - gm);
            s += __shfl_xor_sync(0xffffffffu, s, 1);
            s += __shfl_xor_sync(0xffffffffu, s, 2);
            rsum[r] = s;
        }
        __syncthreads();
        if ((l & 3) == 0) {
            #pragma unroll
            for (int r = 0; r < 4; ++r) {
                const int mt = r >> 1, hf = r & 1;
                const int row = wm * 32 + mt * 16 + hf * 8 + (l >> 2);
                sm_el[wn * 64 + row] = rsum[r];
            }
        }
        __syncthreads();
        if (wn == 0 && (l & 3) == 0) {
            #pragma unroll
            for (int r = 0; r < 4; ++r) {
                const int mt = r >> 1, hf = r & 1;
                const int row = wm * 32 + mt * 16 + hf * 8 + (l >> 2);
                g_tm[tile * BB + row] = rmax[r];
                g_tl[tile * BB + row] = sm_el[row] + sm_el[64 + row]
                                      + sm_el[128 + row] + sm_el[192 + row];
            }
        }
    }
}

// ---------------- kernels ----------------

// split x0 = [emb|lctx] and hprev into bf16 hi/lo
__global__ void prep_kernel(const int* __restrict__ wi,
                            const float* __restrict__ lctx,
                            const float* __restrict__ emb,
                            const float* __restrict__ lhid)
{
    int t = blockIdx.x * blockDim.x + threadIdx.x;   // 196608
    if (t < BB * KIH) {
        int b = t >> 11, k = t & 2047;
        float x = (k < 1024) ? emb[(long)wi[b] * 1024 + k] : lctx[(long)b * HH + (k - 1024)];
        __nv_bfloat16 h = __float2bfloat16(x);
        g_x0hi[t] = h;
        g_x0lo[t] = __float2bfloat16(x - __bfloat162float(h));
    } else {
        int t2 = t - BB * KIH;
        float x = lhid[t2];
        __nv_bfloat16 h = __float2bfloat16(x);
        g_hhi[t2] = h;
        g_hlo[t2] = __float2bfloat16(x - __bfloat162float(h));
    }
}

__global__ void __launch_bounds__(256, 2) gates_mma_kernel(
    const float* __restrict__ wih, const float* __restrict__ whh)
{
    if (blockIdx.x < 48)
        mma_gemm<false>(wih, KIH, g_x0hi, g_x0lo, g_gi, G3H, blockIdx.x * 64, nullptr, 0);
    else
        mma_gemm<false>(whh, HH, g_hhi, g_hlo, g_gh, G3H, (blockIdx.x - 48) * 64, nullptr, 0);
}

__global__ void __launch_bounds__(256, 2) logits_mma_kernel(const float* __restrict__ outW,
                                                            const float* __restrict__ outb)
{
    mma_gemm<true>(outW, KIH, g_zhi, g_zlo, g_logits, VV, blockIdx.x * 64, outb, blockIdx.x);
}

// GRU gate nonlinearity -> h (fp32 + bf16 hi/lo)
__global__ void gru_kernel(const float* __restrict__ bih,
                           const float* __restrict__ bhh,
                           const float* __restrict__ hprev,
                           float* __restrict__ out_hidden)
{
    int t = blockIdx.x * blockDim.x + threadIdx.x;   // 65536
    int b = t >> 10;
    int j = t & 1023;
    const float* gi = g_gi + (long)b * G3H;
    const float* gh = g_gh + (long)b * G3H;
    float r  = 1.f / (1.f + __expf(-((gi[j]        + bih[j])        + (gh[j]        + bhh[j]))));
    float zg = 1.f / (1.f + __expf(-((gi[j + 1024] + bih[j + 1024]) + (gh[j + 1024] + bhh[j + 1024]))));
    float ng = tanhf((gi[j + 2048] + bih[j + 2048]) + r * (gh[j + 2048] + bhh[j + 2048]));
    float hp = hprev[(long)b * HH + j];
    float h  = (1.f - zg) * ng + zg * hp;

    g_z[(long)b * KIH + j] = h;
    out_hidden[(long)b * HH + j] = h;
    __nv_bfloat16 hh = __float2bfloat16(h);
    g_zhi[(long)b * KIH + j] = hh;
    g_zlo[(long)b * KIH + j] = __float2bfloat16(h - __bfloat162float(hh));
}

// warp-independent flash attention: each warp owns 16 s-rows, no syncs in main loop
__global__ void __launch_bounds__(256) attn_kernel(const float* __restrict__ enc)
{
    const int b = blockIdx.x >> 3;
    const int c = blockIdx.x & 7;
    const int tid = threadIdx.x;
    const int w = tid >> 5, l = tid & 31;

    __shared__ float sh_h[HH];
    __shared__ float sm_acc[8][HH];
    __shared__ float sm_m[8], sm_l[8];

    // stage h vector (4KB)
    *(float4*)(sh_h + tid * 4) = *(const float4*)(g_z + (long)b * KIH + tid * 4);
    __syncthreads();

    float m = -INFINITY, lsum = 0.f;
    float4 acc[8];
    #pragma unroll
    for (int q = 0; q < 8; ++q) acc[q] = make_float4(0.f, 0.f, 0.f, 0.f);

    const int sbase = c * 128 + w * 16;
    for (int i = 0; i < 16; ++i) {
        const int s = sbase + i;
        const float* erow = enc + ((long)s * 64 + b) * 1024;
        float4 ev[8];
        #pragma unroll
        for (int q = 0; q < 8; ++q)
            ev[q] = *(const float4*)(erow + q * 128 + l * 4);
        float p = 0.f;
        #pragma unroll
        for (int q = 0; q < 8; ++q) {
            const float4 hv = *(const float4*)(sh_h + q * 128 + l * 4);
            p += ev[q].x * hv.x + ev[q].y * hv.y + ev[q].z * hv.z + ev[q].w * hv.w;
        }
        p = warpRedSum(p);
        if (l == 0) g_energy[(long)b * SS_ + s] = p;

        float mn = fmaxf(m, p);
        float sc = __expf(m - mn);
        float pe = __expf(p - mn);
        lsum = lsum * sc + pe;
        #pragma unroll
        for (int q = 0; q < 8; ++q) {
            acc[q].x = acc[q].x * sc + pe * ev[q].x;
            acc[q].y = acc[q].y * sc + pe * ev[q].y;
            acc[q].z = acc[q].z * sc + pe * ev[q].z;
            acc[q].w = acc[q].w * sc + pe * ev[q].w;
        }
        m = mn;
    }

    // merge 8 warp-partials within the block
    #pragma unroll
    for (int q = 0; q < 8; ++q)
        *(float4*)(&sm_acc[w][q * 128 + l * 4]) = acc[q];
    if (l == 0) { sm_m[w] = m; sm_l[w] = lsum; }
    __syncthreads();

    float M = -INFINITY;
    #pragma unroll
    for (int j = 0; j < 8; ++j) M = fmaxf(M, sm_m[j]);
    float L = 0.f;
    float coef[8];
    #pragma unroll
    for (int j = 0; j < 8; ++j) {
        coef[j] = __expf(sm_m[j] - M);
        L += sm_l[j] * coef[j];
    }

    const int h0 = tid * 4;
    float4 ctx = make_float4(0.f, 0.f, 0.f, 0.f);
    #pragma unroll
    for (int j = 0; j < 8; ++j) {
        float4 pa = *(const float4*)(&sm_acc[j][h0]);
        ctx.x += coef[j] * pa.x;
        ctx.y += coef[j] * pa.y;
        ctx.z += coef[j] * pa.z;
        ctx.w += coef[j] * pa.w;
    }
    *(float4*)(g_pacc + ((long)(b * 8 + c)) * HH + h0) = ctx;
    if (tid == 0) { g_pm[b * 8 + c] = M; g_pl[b * 8 + c] = L; }
}

// merge 8 chunks -> context (fp32 out + bf16 hi/lo into z), attn weights
__global__ void attn_combine(float* __restrict__ out_context,
                             float* __restrict__ out_attn)
{
    int b = blockIdx.x;
    int tid = threadIdx.x;   // 256

    float M = -INFINITY;
    #pragma unroll
    for (int c = 0; c < 8; ++c) M = fmaxf(M, g_pm[b * 8 + c]);
    float L = 0.f;
    float coef[8];
    #pragma unroll
    for (int c = 0; c < 8; ++c) {
        coef[c] = __expf(g_pm[b * 8 + c] - M);
        L += g_pl[b * 8 + c] * coef[c];
    }
    float invL = 1.f / L;

    float4 ctx = make_float4(0.f, 0.f, 0.f, 0.f);
    #pragma unroll
    for (int c = 0; c < 8; ++c) {
        float4 pa = *(const float4*)(g_pacc + ((long)(b * 8 + c)) * HH + tid * 4);
        ctx.x += coef[c] * pa.x;
        ctx.y += coef[c] * pa.y;
        ctx.z += coef[c] * pa.z;
        ctx.w += coef[c] * pa.w;
    }
    ctx.x *= invL; ctx.y *= invL; ctx.z *= invL; ctx.w *= invL;

    *(float4*)(out_context + (long)b * HH + tid * 4) = ctx;
    float cv[4] = {ctx.x, ctx.y, ctx.z, ctx.w};
    #pragma unroll
    for (int q = 0; q < 4; ++q) {
        __nv_bfloat16 h = __float2bfloat16(cv[q]);
        long idx = (long)b * KIH + 1024 + tid * 4 + q;
        g_zhi[idx] = h;
        g_zlo[idx] = __float2bfloat16(cv[q] - __bfloat162float(h));
    }

    for (int s = tid; s < SS_; s += 256) {
        float w = __expf(g_energy[(long)b * SS_ + s] - M) * invL;
        out_attn[(long)b * SS_ + s] = w;
    }
}

// merge per-tile stats -> lse[b]
__global__ void lsm_merge_kernel()
{
    int b = blockIdx.x;
    int tid = threadIdx.x;   // 128
    __shared__ float sm[4];

    float m = -INFINITY;
    for (int t = tid; t < NTILES; t += 128) m = fmaxf(m, g_tm[t * BB + b]);
    m = warpRedMax(m);
    if ((tid & 31) == 0) sm[tid >> 5] = m;
    __syncthreads();
    float M = fmaxf(fmaxf(sm[0], sm[1]), fmaxf(sm[2], sm[3]));
    __syncthreads();

    float s = 0.f;
    for (int t = tid; t < NTILES; t += 128)
        s += g_tl[t * BB + b] * __expf(g_tm[t * BB + b] - M);
    s = warpRedSum(s);
    if ((tid & 31) == 0) sm[tid >> 5] = s;
    __syncthreads();
    if (tid == 0) {
        float S = sm[0] + sm[1] + sm[2] + sm[3];
        g_lse[b] = M + logf(S);
    }
}

// out[b][v] = biased_logits[b][v] - lse[b]
__global__ void lsm_write_kernel(float* __restrict__ out)
{
    int t = blockIdx.x * blockDim.x + threadIdx.x;   // 512000 threads, 4 elems each
    int idx = t * 4;
    int b = idx / VV;
    float lse = g_lse[b];
    float4 v = *(const float4*)(g_logits + idx);
    v.x -= lse; v.y -= lse; v.z -= lse; v.w -= lse;
    *(float4*)(out + idx) = v;
}

// ---------------- launch ----------------
extern "C" void kernel_launch(void* const* d_in, const int* in_sizes, int n_in,
                              void* d_out, int out_size)
{
    const int*   wi   = (const int*)  d_in[0];
    const float* lctx = (const float*)d_in[1];
    const float* lhid = (const float*)d_in[2];
    const float* enc  = (const float*)d_in[3];
    const float* emb  = (const float*)d_in[4];
    const float* wih  = (const float*)d_in[5];
    const float* whh  = (const float*)d_in[6];
    const float* bih  = (const float*)d_in[7];
    const float* bhh  = (const float*)d_in[8];
    const float* outW = (const float*)d_in[9];
    const float* outb = (const float*)d_in[10];

    float* out        = (float*)d_out;
    float* out_output = out;                         // (B, V)
    float* out_ctx    = out + (long)BB * VV;         // (B, H)
    float* out_hid    = out_ctx + (long)BB * HH;     // (1, B, H)
    float* out_attn   = out_hid + (long)BB * HH;     // (B, 1, S)

    cudaFuncSetAttribute(gates_mma_kernel,  cudaFuncAttributeMaxDynamicSharedMemorySize, SMEM_GEMM);
    cudaFuncSetAttribute(logits_mma_kernel, cudaFuncAttributeMaxDynamicSharedMemorySize, SMEM_GEMM);

    prep_kernel      <<<768, 256>>>(wi, lctx, emb, lhid);
    gates_mma_kernel <<<96, 256, SMEM_GEMM>>>(wih, whh);
    gru_kernel       <<<256, 256>>>(bih, bhh, lhid, out_hid);
    attn_kernel      <<<512, 256>>>(enc);
    attn_combine     <<<64, 256>>>(out_ctx, out_attn);
    logits_mma_kernel<<<NTILES, 256, SMEM_GEMM>>>(outW, outb);
    lsm_merge_kernel <<<64, 128>>>();
    lsm_write_kernel <<<2000, 256>>>(out_output);
}

// round 6
// speedup vs baseline: 6.8630x; 1.2221x over previous
#include <cuda_runtime.h>
#include <cuda_bf16.h>
#include <math.h>
#include <stdint.h>

// Problem constants
#define BB 64
#define HH 1024
#define SS_ 1024
#define VV 32000
#define KIH 2048   // E + H
#define G3H 3072   // 3*H
#define NTILES 250 // logits tiles of 128 cols

// ---------------- scratch (static device globals) ----------------
__device__ __nv_bfloat16 g_x0hi[BB * KIH];
__device__ __nv_bfloat16 g_x0lo[BB * KIH];
__device__ __nv_bfloat16 g_hhi [BB * HH];
__device__ __nv_bfloat16 g_hlo [BB * HH];
__device__ __nv_bfloat16 g_zhi [BB * KIH];   // [b][ h | ctx ]
__device__ __nv_bfloat16 g_zlo [BB * KIH];
__device__ float g_gi[BB * G3H];             // [b][n]
__device__ float g_gh[BB * G3H];             // [b][n]
__device__ float g_z [BB * KIH];             // fp32 h (attn uses [0,1024))
__device__ float g_energy[BB * SS_];
__device__ float g_pm[BB * 8];
__device__ float g_pl[BB * 8];
__device__ float g_pacc[BB * 8 * HH];
__device__ float g_logits[BB * VV];          // biased logits
__device__ float g_tm[NTILES * BB];          // per-tile row max
__device__ float g_tl[NTILES * BB];          // per-tile row sumexp
__device__ float g_lse[BB];

// ---------------- helpers ----------------
__device__ __forceinline__ uint32_t smem_u32(const void* p) {
    uint32_t a;
    asm("{ .reg .u64 t; cvta.to.shared.u64 t, %1; cvt.u32.u64 %0, t; }" : "=r"(a) : "l"(p));
    return a;
}
__device__ __forceinline__ void ldm_x4(uint32_t& r0, uint32_t& r1, uint32_t& r2, uint32_t& r3,
                                       uint32_t addr) {
    asm volatile("ldmatrix.sync.aligned.m8n8.x4.shared.b16 {%0,%1,%2,%3}, [%4];"
        : "=r"(r0), "=r"(r1), "=r"(r2), "=r"(r3) : "r"(addr));
}
__device__ __forceinline__ void mma_bf16(float* c, const uint32_t* a, const uint32_t* b) {
    asm volatile("mma.sync.aligned.m16n8k16.row.col.f32.bf16.bf16.f32 "
        "{%0,%1,%2,%3}, {%4,%5,%6,%7}, {%8,%9}, {%0,%1,%2,%3};"
        : "+f"(c[0]), "+f"(c[1]), "+f"(c[2]), "+f"(c[3])
        : "r"(a[0]), "r"(a[1]), "r"(a[2]), "r"(a[3]), "r"(b[0]), "r"(b[1]));
}
__device__ __forceinline__ uint2 cvt_hi_pair(float4 x) {
    __nv_bfloat162 h0 = __floats2bfloat162_rn(x.x, x.y);
    __nv_bfloat162 h1 = __floats2bfloat162_rn(x.z, x.w);
    uint2 r; r.x = *(uint32_t*)&h0; r.y = *(uint32_t*)&h1;
    return r;
}

__device__ __forceinline__ float warpRedSum(float v) {
    #pragma unroll
    for (int o = 16; o; o >>= 1) v += __shfl_xor_sync(0xffffffffu, v, o);
    return v;
}
__device__ __forceinline__ float warpRedMax(float v) {
    #pragma unroll
    for (int o = 16; o; o >>= 1) v = fmaxf(v, __shfl_xor_sync(0xffffffffu, v, o));
    return v;
}

// ================= gates GEMM (3-product split bf16, unchanged geometry) =================
#define PITCH  72                      // bf16 elements per smem row (144 B)
#define ABYTES (128 * PITCH * 2)       // 18432: 64 hi rows + 64 lo rows
#define WOFF   ABYTES
#define BUFSZ  (2 * ABYTES)            // 36864 per buffer (A + W)
#define SMEM_GEMM (2 * BUFSZ)          // 73728 double-buffered

__device__ __forceinline__ void mma_gemm3(
    const float* __restrict__ W, int K,
    const __nv_bfloat16* __restrict__ Ahi, const __nv_bfloat16* __restrict__ Alo,
    float* __restrict__ OUT, int ldout, int n0)
{
    extern __shared__ char smem[];
    const uint32_t sbase = smem_u32(smem);
    const int tid = threadIdx.x;
    const int w = tid >> 5, l = tid & 31;
    const int wm = w >> 2;
    const int wn = w & 3;
    const int nch = K >> 6;

    const int ar   = tid >> 1;
    const int aseg = (tid & 1) * 32;
    const __nv_bfloat16* asrc =
        (ar < 64 ? Ahi + (long)ar * K : Alo + (long)(ar - 64) * K) + aseg;
    const int adst = (ar * PITCH + aseg) * 2;

    const int wr   = tid >> 2;
    const int wseg = (tid & 3) * 16;
    const float* wsrc = W + (long)(n0 + wr) * K + wseg;
    const int wdst_hi = (wr * PITCH + wseg) * 2;
    const int wdst_lo = ((wr + 64) * PITCH + wseg) * 2;

    float acc[2][2][4];
    #pragma unroll
    for (int i = 0; i < 2; ++i)
        #pragma unroll
        for (int j = 0; j < 2; ++j)
            #pragma unroll
            for (int q = 0; q < 4; ++q) acc[i][j][q] = 0.f;

    uint4  stA[4];
    float4 stW[4];

    #pragma unroll
    for (int i = 0; i < 4; ++i) stA[i] = *(const uint4*)(asrc + i * 8);
    #pragma unroll
    for (int i = 0; i < 4; ++i) stW[i] = *(const float4*)(wsrc + i * 4);
    {
        char* bufA = smem;
        char* bufW = smem + WOFF;
        #pragma unroll
        for (int i = 0; i < 4; ++i) *(uint4*)(bufA + adst + i * 16) = stA[i];
        #pragma unroll
        for (int i = 0; i < 4; ++i) {
            float4 x = stW[i];
            uint2 hp = cvt_hi_pair(x);
            __nv_bfloat162 h0 = *(__nv_bfloat162*)&hp.x;
            __nv_bfloat162 h1 = *(__nv_bfloat162*)&hp.y;
            __nv_bfloat162 l0 = __floats2bfloat162_rn(x.x - __bfloat162float(h0.x),
                                                      x.y - __bfloat162float(h0.y));
            __nv_bfloat162 l1 = __floats2bfloat162_rn(x.z - __bfloat162float(h1.x),
                                                      x.w - __bfloat162float(h1.y));
            uint2 lp; lp.x = *(uint32_t*)&l0; lp.y = *(uint32_t*)&l1;
            *(uint2*)(bufW + wdst_hi + i * 8) = hp;
            *(uint2*)(bufW + wdst_lo + i * 8) = lp;
        }
    }
    __syncthreads();

    for (int c = 0; c < nch; ++c) {
        const int cur = c & 1;
        if (c + 1 < nch) {
            const __nv_bfloat16* as = asrc + (c + 1) * 64;
            #pragma unroll
            for (int i = 0; i < 4; ++i) stA[i] = *(const uint4*)(as + i * 8);
            const float* ws = wsrc + (c + 1) * 64;
            #pragma unroll
            for (int i = 0; i < 4; ++i) stW[i] = *(const float4*)(ws + i * 4);
        }
        const uint32_t sA = sbase + cur * BUFSZ;
        const uint32_t sW = sA + WOFF;

        #pragma unroll
        for (int ks = 0; ks < 4; ++ks) {
            const int k = ks * 16;
            uint32_t ah[2][4], al[2][4], bh[4], bl[4];
            const int rowa = l & 15;
            const int cola = k + (l >> 4) * 8;
            #pragma unroll
            for (int mt = 0; mt < 2; ++mt) {
                const int rhi = wm * 32 + mt * 16 + rowa;
                ldm_x4(ah[mt][0], ah[mt][1], ah[mt][2], ah[mt][3],
                       sA + (rhi * PITCH + cola) * 2);
                ldm_x4(al[mt][0], al[mt][1], al[mt][2], al[mt][3],
                       sA + ((rhi + 64) * PITCH + cola) * 2);
            }
            const int rowb = wn * 16 + ((l >> 4) << 3) + (l & 7);
            const int colb = k + ((l >> 3) & 1) * 8;
            ldm_x4(bh[0], bh[1], bh[2], bh[3], sW + (rowb * PITCH + colb) * 2);
            ldm_x4(bl[0], bl[1], bl[2], bl[3], sW + ((rowb + 64) * PITCH + colb) * 2);

            #pragma unroll
            for (int mt = 0; mt < 2; ++mt)
                #pragma unroll
                for (int nt = 0; nt < 2; ++nt) {
                    mma_bf16(acc[mt][nt], ah[mt], &bh[nt * 2]);
                    mma_bf16(acc[mt][nt], ah[mt], &bl[nt * 2]);
                    mma_bf16(acc[mt][nt], al[mt], &bh[nt * 2]);
                }
        }

        if (c + 1 < nch) {
            char* bufA = smem + (cur ^ 1) * BUFSZ;
            char* bufW = bufA + WOFF;
            #pragma unroll
            for (int i = 0; i < 4; ++i) *(uint4*)(bufA + adst + i * 16) = stA[i];
            #pragma unroll
            for (int i = 0; i < 4; ++i) {
                float4 x = stW[i];
                uint2 hp = cvt_hi_pair(x);
                __nv_bfloat162 h0 = *(__nv_bfloat162*)&hp.x;
                __nv_bfloat162 h1 = *(__nv_bfloat162*)&hp.y;
                __nv_bfloat162 l0 = __floats2bfloat162_rn(x.x - __bfloat162float(h0.x),
                                                          x.y - __bfloat162float(h0.y));
                __nv_bfloat162 l1 = __floats2bfloat162_rn(x.z - __bfloat162float(h1.x),
                                                          x.w - __bfloat162float(h1.y));
                uint2 lp; lp.x = *(uint32_t*)&l0; lp.y = *(uint32_t*)&l1;
                *(uint2*)(bufW + wdst_hi + i * 8) = hp;
                *(uint2*)(bufW + wdst_lo + i * 8) = lp;
            }
        }
        __syncthreads();
    }

    #pragma unroll
    for (int mt = 0; mt < 2; ++mt) {
        #pragma unroll
        for (int nt = 0; nt < 2; ++nt) {
            const int row = wm * 32 + mt * 16 + (l >> 2);
            const int col = n0 + wn * 16 + nt * 8 + (l & 3) * 2;
            *(float2*)(OUT + (long)row * ldout + col)       = make_float2(acc[mt][nt][0], acc[mt][nt][1]);
            *(float2*)(OUT + (long)(row + 8) * ldout + col) = make_float2(acc[mt][nt][2], acc[mt][nt][3]);
        }
    }
}

__global__ void __launch_bounds__(256, 2) gates_mma_kernel(
    const float* __restrict__ wih, const float* __restrict__ whh)
{
    if (blockIdx.x < 48)
        mma_gemm3(wih, KIH, g_x0hi, g_x0lo, g_gi, G3H, blockIdx.x * 64);
    else
        mma_gemm3(whh, HH, g_hhi, g_hlo, g_gh, G3H, (blockIdx.x - 48) * 64);
}

// ================= logits GEMM: single-product bf16, M=64 x N=128 tile =================
// smem per buffer: A 64x72 bf16 (9216 B) + W 128x72 bf16 (18432 B)
#define L_AOFF   0
#define L_WOFF   9216
#define L_BUFSZ  27648
#define SMEM_LOG (2 * L_BUFSZ)   // 55296

__global__ void __launch_bounds__(256, 2) logits_mma_kernel(const float* __restrict__ outW,
                                                            const float* __restrict__ outb)
{
    extern __shared__ char smem[];
    const uint32_t sbase = smem_u32(smem);
    const int tid = threadIdx.x;
    const int w = tid >> 5, l = tid & 31;
    const int wm = w >> 2;          // 0/1 : rows wm*32..+31
    const int wn = w & 3;           // 0..3: cols wn*32..+31
    const int tile = blockIdx.x;
    const int n0 = tile * 128;
    const int nch = KIH >> 6;       // 32

    // A staging: row = tid>>2 (0..63), 16 bf16 per thread
    const int ar   = tid >> 2;
    const int aseg = (tid & 3) * 16;
    const __nv_bfloat16* asrc = g_zhi + (long)ar * KIH + aseg;
    const int adst = (ar * PITCH + aseg) * 2;

    // W staging: row = tid>>1 (0..127), 32 floats per thread -> 32 bf16 (hi only)
    const int wr   = tid >> 1;
    const int wseg = (tid & 1) * 32;
    const float* wsrc = outW + (long)(n0 + wr) * KIH + wseg;
    const int wdst = (wr * PITCH + wseg) * 2;

    float acc[2][4][4];
    #pragma unroll
    for (int i = 0; i < 2; ++i)
        #pragma unroll
        for (int j = 0; j < 4; ++j)
            #pragma unroll
            for (int q = 0; q < 4; ++q) acc[i][j][q] = 0.f;

    uint4  stA[2];
    float4 stW[8];

    // prologue: chunk 0
    #pragma unroll
    for (int i = 0; i < 2; ++i) stA[i] = *(const uint4*)(asrc + i * 8);
    #pragma unroll
    for (int i = 0; i < 8; ++i) stW[i] = *(const float4*)(wsrc + i * 4);
    {
        char* bufA = smem + L_AOFF;
        char* bufW = smem + L_WOFF;
        #pragma unroll
        for (int i = 0; i < 2; ++i) *(uint4*)(bufA + adst + i * 16) = stA[i];
        #pragma unroll
        for (int i = 0; i < 4; ++i) {
            uint2 p0 = cvt_hi_pair(stW[i * 2]);
            uint2 p1 = cvt_hi_pair(stW[i * 2 + 1]);
            *(uint4*)(bufW + wdst + i * 16) = make_uint4(p0.x, p0.y, p1.x, p1.y);
        }
    }
    __syncthreads();

    for (int c = 0; c < nch; ++c) {
        const int cur = c & 1;
        if (c + 1 < nch) {
            const __nv_bfloat16* as = asrc + (c + 1) * 64;
            #pragma unroll
            for (int i = 0; i < 2; ++i) stA[i] = *(const uint4*)(as + i * 8);
            const float* ws = wsrc + (c + 1) * 64;
            #pragma unroll
            for (int i = 0; i < 8; ++i) stW[i] = *(const float4*)(ws + i * 4);
        }
        const uint32_t sA = sbase + cur * L_BUFSZ + L_AOFF;
        const uint32_t sW = sbase + cur * L_BUFSZ + L_WOFF;

        #pragma unroll
        for (int ks = 0; ks < 4; ++ks) {
            const int k = ks * 16;
            uint32_t ah[2][4], bh[2][4];
            const int rowa = l & 15;
            const int cola = k + (l >> 4) * 8;
            #pragma unroll
            for (int mt = 0; mt < 2; ++mt) {
                const int rhi = wm * 32 + mt * 16 + rowa;
                ldm_x4(ah[mt][0], ah[mt][1], ah[mt][2], ah[mt][3],
                       sA + (rhi * PITCH + cola) * 2);
            }
            const int colb = k + ((l >> 3) & 1) * 8;
            #pragma unroll
            for (int np = 0; np < 2; ++np) {
                const int rowb = wn * 32 + np * 16 + ((l >> 4) << 3) + (l & 7);
                ldm_x4(bh[np][0], bh[np][1], bh[np][2], bh[np][3],
                       sW + (rowb * PITCH + colb) * 2);
            }
            #pragma unroll
            for (int mt = 0; mt < 2; ++mt)
                #pragma unroll
                for (int nt = 0; nt < 4; ++nt)
                    mma_bf16(acc[mt][nt], ah[mt], &bh[nt >> 1][(nt & 1) * 2]);
        }

        if (c + 1 < nch) {
            char* bufA = smem + (cur ^ 1) * L_BUFSZ + L_AOFF;
            char* bufW = smem + (cur ^ 1) * L_BUFSZ + L_WOFF;
            #pragma unroll
            for (int i = 0; i < 2; ++i) *(uint4*)(bufA + adst + i * 16) = stA[i];
            #pragma unroll
            for (int i = 0; i < 4; ++i) {
                uint2 p0 = cvt_hi_pair(stW[i * 2]);
                uint2 p1 = cvt_hi_pair(stW[i * 2 + 1]);
                *(uint4*)(bufW + wdst + i * 16) = make_uint4(p0.x, p0.y, p1.x, p1.y);
            }
        }
        __syncthreads();
    }

    // bias add
    #pragma unroll
    for (int nt = 0; nt < 4; ++nt) {
        const int col = n0 + wn * 32 + nt * 8 + (l & 3) * 2;
        float2 bb = *(const float2*)(outb + col);
        #pragma unroll
        for (int mt = 0; mt < 2; ++mt) {
            acc[mt][nt][0] += bb.x; acc[mt][nt][1] += bb.y;
            acc[mt][nt][2] += bb.x; acc[mt][nt][3] += bb.y;
        }
    }

    // store biased logits
    #pragma unroll
    for (int mt = 0; mt < 2; ++mt) {
        #pragma unroll
        for (int nt = 0; nt < 4; ++nt) {
            const int row = wm * 32 + mt * 16 + (l >> 2);
            const int col = n0 + wn * 32 + nt * 8 + (l & 3) * 2;
            *(float2*)(g_logits + (long)row * VV + col)       = make_float2(acc[mt][nt][0], acc[mt][nt][1]);
            *(float2*)(g_logits + (long)(row + 8) * VV + col) = make_float2(acc[mt][nt][2], acc[mt][nt][3]);
        }
    }

    // per-row tile stats (max + sumexp over 128 cols)
    {
        float* sm_em = (float*)smem;         // [4][64]
        float* sm_el = sm_em + 256;          // [4][64]
        float rmax[4], rsum[4];
        #pragma unroll
        for (int r = 0; r < 4; ++r) {
            const int mt = r >> 1, hf = r & 1;
            float v = -INFINITY;
            #pragma unroll
            for (int nt = 0; nt < 4; ++nt)
                v = fmaxf(v, fmaxf(acc[mt][nt][hf * 2], acc[mt][nt][hf * 2 + 1]));
            v = fmaxf(v, __shfl_xor_sync(0xffffffffu, v, 1));
            v = fmaxf(v, __shfl_xor_sync(0xffffffffu, v, 2));
            rmax[r] = v;
        }
        __syncthreads();   // smem reuse after GEMM buffers
        if ((l & 3) == 0) {
            #pragma unroll
            for (int r = 0; r < 4; ++r) {
                const int mt = r >> 1, hf = r & 1;
                const int row = wm * 32 + mt * 16 + hf * 8 + (l >> 2);
                sm_em[wn * 64 + row] = rmax[r];
            }
        }
        __syncthreads();
        #pragma unroll
        for (int r = 0; r < 4; ++r) {
            const int mt = r >> 1, hf = r & 1;
            const int row = wm * 32 + mt * 16 + hf * 8 + (l >> 2);
            float gm = fmaxf(fmaxf(sm_em[row], sm_em[64 + row]),
                             fmaxf(sm_em[128 + row], sm_em[192 + row]));
            rmax[r] = gm;
            float s = 0.f;
            #pragma unroll
            for (int nt = 0; nt < 4; ++nt)
                s += __expf(acc[mt][nt][hf * 2] - gm) + __expf(acc[mt][nt][hf * 2 + 1] - gm);
            s += __shfl_xor_sync(0xffffffffu, s, 1);
            s += __shfl_xor_sync(0xffffffffu, s, 2);
            rsum[r] = s;
        }
        __syncthreads();
        if ((l & 3) == 0) {
            #pragma unroll
            for (int r = 0; r < 4; ++r) {
                const int mt = r >> 1, hf = r & 1;
                const int row = wm * 32 + mt * 16 + hf * 8 + (l >> 2);
                sm_el[wn * 64 + row] = rsum[r];
            }
        }
        __syncthreads();
        if (wn == 0 && (l & 3) == 0) {
            #pragma unroll
            for (int r = 0; r < 4; ++r) {
                const int mt = r >> 1, hf = r & 1;
                const int row = wm * 32 + mt * 16 + hf * 8 + (l >> 2);
                g_tm[tile * BB + row] = rmax[r];
                g_tl[tile * BB + row] = sm_el[row] + sm_el[64 + row]
                                      + sm_el[128 + row] + sm_el[192 + row];
            }
        }
    }
}

// ---------------- kernels ----------------

// split x0 = [emb|lctx] and hprev into bf16 hi/lo
__global__ void prep_kernel(const int* __restrict__ wi,
                            const float* __restrict__ lctx,
                            const float* __restrict__ emb,
                            const float* __restrict__ lhid)
{
    int t = blockIdx.x * blockDim.x + threadIdx.x;   // 196608
    if (t < BB * KIH) {
        int b = t >> 11, k = t & 2047;
        float x = (k < 1024) ? emb[(long)wi[b] * 1024 + k] : lctx[(long)b * HH + (k - 1024)];
        __nv_bfloat16 h = __float2bfloat16(x);
        g_x0hi[t] = h;
        g_x0lo[t] = __float2bfloat16(x - __bfloat162float(h));
    } else {
        int t2 = t - BB * KIH;
        float x = lhid[t2];
        __nv_bfloat16 h = __float2bfloat16(x);
        g_hhi[t2] = h;
        g_hlo[t2] = __float2bfloat16(x - __bfloat162float(h));
    }
}

// GRU gate nonlinearity -> h (fp32 + bf16 hi/lo)
__global__ void gru_kernel(const float* __restrict__ bih,
                           const float* __restrict__ bhh,
                           const float* __restrict__ hprev,
                           float* __restrict__ out_hidden)
{
    int t = blockIdx.x * blockDim.x + threadIdx.x;   // 65536
    int b = t >> 10;
    int j = t & 1023;
    const float* gi = g_gi + (long)b * G3H;
    const float* gh = g_gh + (long)b * G3H;
    float r  = 1.f / (1.f + __expf(-((gi[j]        + bih[j])        + (gh[j]        + bhh[j]))));
    float zg = 1.f / (1.f + __expf(-((gi[j + 1024] + bih[j + 1024]) + (gh[j + 1024] + bhh[j + 1024]))));
    float ng = tanhf((gi[j + 2048] + bih[j + 2048]) + r * (gh[j + 2048] + bhh[j + 2048]));
    float hp = hprev[(long)b * HH + j];
    float h  = (1.f - zg) * ng + zg * hp;

    g_z[(long)b * KIH + j] = h;
    out_hidden[(long)b * HH + j] = h;
    __nv_bfloat16 hh = __float2bfloat16(h);
    g_zhi[(long)b * KIH + j] = hh;
    g_zlo[(long)b * KIH + j] = __float2bfloat16(h - __bfloat162float(hh));
}

// warp-independent flash attention: each warp owns 16 s-rows, no syncs in main loop
__global__ void __launch_bounds__(256) attn_kernel(const float* __restrict__ enc)
{
    const int b = blockIdx.x >> 3;
    const int c = blockIdx.x & 7;
    const int tid = threadIdx.x;
    const int w = tid >> 5, l = tid & 31;

    __shared__ float sh_h[HH];
    __shared__ float sm_acc[8][HH];
    __shared__ float sm_m[8], sm_l[8];

    *(float4*)(sh_h + tid * 4) = *(const float4*)(g_z + (long)b * KIH + tid * 4);
    __syncthreads();

    float m = -INFINITY, lsum = 0.f;
    float4 acc[8];
    #pragma unroll
    for (int q = 0; q < 8; ++q) acc[q] = make_float4(0.f, 0.f, 0.f, 0.f);

    const int sbase = c * 128 + w * 16;
    for (int i = 0; i < 16; ++i) {
        const int s = sbase + i;
        const float* erow = enc + ((long)s * 64 + b) * 1024;
        float4 ev[8];
        #pragma unroll
        for (int q = 0; q < 8; ++q)
            ev[q] = *(const float4*)(erow + q * 128 + l * 4);
        float p = 0.f;
        #pragma unroll
        for (int q = 0; q < 8; ++q) {
            const float4 hv = *(const float4*)(sh_h + q * 128 + l * 4);
            p += ev[q].x * hv.x + ev[q].y * hv.y + ev[q].z * hv.z + ev[q].w * hv.w;
        }
        p = warpRedSum(p);
        if (l == 0) g_energy[(long)b * SS_ + s] = p;

        float mn = fmaxf(m, p);
        float sc = __expf(m - mn);
        float pe = __expf(p - mn);
        lsum = lsum * sc + pe;
        #pragma unroll
        for (int q = 0; q < 8; ++q) {
            acc[q].x = acc[q].x * sc + pe * ev[q].x;
            acc[q].y = acc[q].y * sc + pe * ev[q].y;
            acc[q].z = acc[q].z * sc + pe * ev[q].z;
            acc[q].w = acc[q].w * sc + pe * ev[q].w;
        }
        m = mn;
    }

    #pragma unroll
    for (int q = 0; q < 8; ++q)
        *(float4*)(&sm_acc[w][q * 128 + l * 4]) = acc[q];
    if (l == 0) { sm_m[w] = m; sm_l[w] = lsum; }
    __syncthreads();

    float M = -INFINITY;
    #pragma unroll
    for (int j = 0; j < 8; ++j) M = fmaxf(M, sm_m[j]);
    float L = 0.f;
    float coef[8];
    #pragma unroll
    for (int j = 0; j < 8; ++j) {
        coef[j] = __expf(sm_m[j] - M);
        L += sm_l[j] * coef[j];
    }

    const int h0 = tid * 4;
    float4 ctx = make_float4(0.f, 0.f, 0.f, 0.f);
    #pragma unroll
    for (int j = 0; j < 8; ++j) {
        float4 pa = *(const float4*)(&sm_acc[j][h0]);
        ctx.x += coef[j] * pa.x;
        ctx.y += coef[j] * pa.y;
        ctx.z += coef[j] * pa.z;
        ctx.w += coef[j] * pa.w;
    }
    *(float4*)(g_pacc + ((long)(b * 8 + c)) * HH + h0) = ctx;
    if (tid == 0) { g_pm[b * 8 + c] = M; g_pl[b * 8 + c] = L; }
}

// merge 8 chunks -> context (fp32 out + bf16 hi/lo into z), attn weights
__global__ void attn_combine(float* __restrict__ out_context,
                             float* __restrict__ out_attn)
{
    int b = blockIdx.x;
    int tid = threadIdx.x;   // 256

    float M = -INFINITY;
    #pragma unroll
    for (int c = 0; c < 8; ++c) M = fmaxf(M, g_pm[b * 8 + c]);
    float L = 0.f;
    float coef[8];
    #pragma unroll
    for (int c = 0; c < 8; ++c) {
        coef[c] = __expf(g_pm[b * 8 + c] - M);
        L += g_pl[b * 8 + c] * coef[c];
    }
    float invL = 1.f / L;

    float4 ctx = make_float4(0.f, 0.f, 0.f, 0.f);
    #pragma unroll
    for (int c = 0; c < 8; ++c) {
        float4 pa = *(const float4*)(g_pacc + ((long)(b * 8 + c)) * HH + tid * 4);
        ctx.x += coef[c] * pa.x;
        ctx.y += coef[c] * pa.y;
        ctx.z += coef[c] * pa.z;
        ctx.w += coef[c] * pa.w;
    }
    ctx.x *= invL; ctx.y *= invL; ctx.z *= invL; ctx.w *= invL;

    *(float4*)(out_context + (long)b * HH + tid * 4) = ctx;
    float cv[4] = {ctx.x, ctx.y, ctx.z, ctx.w};
    #pragma unroll
    for (int q = 0; q < 4; ++q) {
        __nv_bfloat16 h = __float2bfloat16(cv[q]);
        long idx = (long)b * KIH + 1024 + tid * 4 + q;
        g_zhi[idx] = h;
        g_zlo[idx] = __float2bfloat16(cv[q] - __bfloat162float(h));
    }

    for (int s = tid; s < SS_; s += 256) {
        float w = __expf(g_energy[(long)b * SS_ + s] - M) * invL;
        out_attn[(long)b * SS_ + s] = w;
    }
}

// merge per-tile stats -> lse[b]
__global__ void lsm_merge_kernel()
{
    int b = blockIdx.x;
    int tid = threadIdx.x;   // 128
    __shared__ float sm[4];

    float m = -INFINITY;
    for (int t = tid; t < NTILES; t += 128) m = fmaxf(m, g_tm[t * BB + b]);
    m = warpRedMax(m);
    if ((tid & 31) == 0) sm[tid >> 5] = m;
    __syncthreads();
    float M = fmaxf(fmaxf(sm[0], sm[1]), fmaxf(sm[2], sm[3]));
    __syncthreads();

    float s = 0.f;
    for (int t = tid; t < NTILES; t += 128)
        s += g_tl[t * BB + b] * __expf(g_tm[t * BB + b] - M);
    s = warpRedSum(s);
    if ((tid & 31) == 0) sm[tid >> 5] = s;
    __syncthreads();
    if (tid == 0) {
        float S = sm[0] + sm[1] + sm[2] + sm[3];
        g_lse[b] = M + logf(S);
    }
}

// out[b][v] = biased_logits[b][v] - lse[b]
__global__ void lsm_write_kernel(float* __restrict__ out)
{
    int t = blockIdx.x * blockDim.x + threadIdx.x;   // 512000 threads, 4 elems each
    int idx = t * 4;
    int b = idx / VV;
    float lse = g_lse[b];
    float4 v = *(const float4*)(g_logits + idx);
    v.x -= lse; v.y -= lse; v.z -= lse; v.w -= lse;
    *(float4*)(out + idx) = v;
}

// ---------------- launch ----------------
extern "C" void kernel_launch(void* const* d_in, const int* in_sizes, int n_in,
                              void* d_out, int out_size)
{
    const int*   wi   = (const int*)  d_in[0];
    const float* lctx = (const float*)d_in[1];
    const float* lhid = (const float*)d_in[2];
    const float* enc  = (const float*)d_in[3];
    const float* emb  = (const float*)d_in[4];
    const float* wih  = (const float*)d_in[5];
    const float* whh  = (const float*)d_in[6];
    const float* bih  = (const float*)d_in[7];
    const float* bhh  = (const float*)d_in[8];
    const float* outW = (const float*)d_in[9];
    const float* outb = (const float*)d_in[10];

    float* out        = (float*)d_out;
    float* out_output = out;                         // (B, V)
    float* out_ctx    = out + (long)BB * VV;         // (B, H)
    float* out_hid    = out_ctx + (long)BB * HH;     // (1, B, H)
    float* out_attn   = out_hid + (long)BB * HH;     // (B, 1, S)

    cudaFuncSetAttribute(gates_mma_kernel,  cudaFuncAttributeMaxDynamicSharedMemorySize, SMEM_GEMM);
    cudaFuncSetAttribute(logits_mma_kernel, cudaFuncAttributeMaxDynamicSharedMemorySize, SMEM_LOG);

    prep_kernel      <<<768, 256>>>(wi, lctx, emb, lhid);
    gates_mma_kernel <<<96, 256, SMEM_GEMM>>>(wih, whh);
    gru_kernel       <<<256, 256>>>(bih, bhh, lhid, out_hid);
    attn_kernel      <<<512, 256>>>(enc);
    attn_combine     <<<64, 256>>>(out_ctx, out_attn);
    logits_mma_kernel<<<NTILES, 256, SMEM_LOG>>>(outW, outb);
    lsm_merge_kernel <<<64, 128>>>();
    lsm_write_kernel <<<2000, 256>>>(out_output);
}